// round 7
// baseline (speedup 1.0000x reference)
#include <cuda_runtime.h>

#define EPSF 1e-8f
#define LNK   16
#define DST   255
#define TUN   1020
#define NCH   8
#define PAIRS 16          // row pairs per block
#define ROWS  32
#define SSTR  34          // words per group slot (16 pairs*2 + 2 pad)
#define PLW   (32*SSTR)   // 1088 words per plane
#define BUFW  (4*PLW)     // 4352 data words per buffer
#define BUFWZ (BUFW+64)   // + 64-word zero region (dummy target for all 32 lanes)
#define BUFB  (BUFWZ*4)   // 17664 bytes buffer stride
#define ZOFF  (BUFW*4)    // 17408: zero region byte offset (same in both buffers)
#define SCHW  144
#define THR   512

__device__ float    g_partials[512];
__device__ unsigned g_count;   // zero-init; last block resets (deterministic)

__device__ __forceinline__ unsigned long long lds64(unsigned a) {
    unsigned long long v;
    asm volatile("ld.shared.b64 %0, [%1];" : "=l"(v) : "r"(a));
    return v;
}
__device__ __forceinline__ unsigned long long addx2(unsigned long long a,
                                                    unsigned long long b) {
    unsigned long long r;
    asm("add.rn.f32x2 %0, %1, %2;" : "=l"(r) : "l"(a), "l"(b));
    return r;
}

__global__ __launch_bounds__(THR, 3) void loss_kernel(
    const float* __restrict__ pred,   // [B,1020]
    const float* __restrict__ dem,    // [B,255]
    const float* __restrict__ clu,    // [B,16]
    const float* __restrict__ caps,   // [16]
    const int*   __restrict__ t2l,    // [1020]
    float* __restrict__ out,
    int B, int nb, float invB)
{
    __shared__ float s_pl[2][BUFWZ];                // double-buffered planes + zero regions
    __shared__ unsigned short s_sched[NCH * SCHW];
    __shared__ int   s_off[NCH][17];
    __shared__ int   s_cur[NCH][17];
    __shared__ float s_nl[ROWS * 17];
    __shared__ float s_inv[LNK];
    __shared__ float s_loss[16];
    __shared__ float s_fin[THR];
    __shared__ int   s_last;

    const int tid  = threadIdx.x;
    const int warp = tid >> 5;          // 0..15; stages pair=warp, gathers bin=warp
    const int lane = tid & 31;
    const int base = blockIdx.x * ROWS;
    const unsigned pl32 = (unsigned)__cvta_generic_to_shared(s_pl);

    float4 ra, rb; float da, db;        // staged pair (rows base+warp, base+warp+16)

    // ------------- LDG chunk 0 --------------------------------------------
    {
        const int r0 = base + warp, r1 = base + warp + PAIRS;
        const bool o0 = (r0 < B), o1 = (r1 < B);
        ra = o0 ? ((const float4*)pred)[(size_t)r0 * DST + lane] : make_float4(0,0,0,0);
        rb = o1 ? ((const float4*)pred)[(size_t)r1 * DST + lane] : make_float4(0,0,0,0);
        da = o0 ? dem[(size_t)r0 * DST + lane] : 0.0f;
        db = o1 ? dem[(size_t)r1 * DST + lane] : 0.0f;
    }

    // ------------- schedule build: warp c (<8) sorts chunk c ---------------
    if (warp < 8) {
        const int c = warp;
        if (lane < 17) s_cur[c][lane] = 0;
        int bins[4];
        #pragma unroll
        for (int q = 0; q < 4; ++q) {
            const int t = c * 128 + q * 32 + lane;
            bins[q] = (t < TUN) ? t2l[t] : 16;
        }
        __syncwarp();
        #pragma unroll
        for (int q = 0; q < 4; ++q) {
            const unsigned peers = __match_any_sync(0xffffffffu, bins[q]);
            const int rank = __popc(peers & ((1u << lane) - 1u));
            if (rank == 0) s_cur[c][bins[q]] += __popc(peers);
            __syncwarp();
        }
        if (lane < 17) {                           // padded exclusive scan
            int o = 0;
            for (int i = 0; i < lane; ++i) o += (s_cur[c][i] + 1) & ~1;
            s_off[c][lane] = o;
        }
        __syncwarp();
        for (int i = lane; i < SCHW; i += 32)
            s_sched[c * SCHW + i] = (unsigned short)ZOFF;   // dummy -> zero region
        if (lane < 17) s_cur[c][lane] = s_off[c][lane];
        __syncwarp();
        #pragma unroll
        for (int q = 0; q < 4; ++q) {
            const unsigned peers = __match_any_sync(0xffffffffu, bins[q]);
            const int rank = __popc(peers & ((1u << lane) - 1u));
            const int bse  = s_cur[c][bins[q]];
            __syncwarp();
            if (rank == 0) s_cur[c][bins[q]] = bse + __popc(peers);
            __syncwarp();
            if (bins[q] < 16) {
                const int tl = q * 32 + lane;
                const unsigned off = (unsigned)(tl & 3) * (PLW * 4)
                                   + (unsigned)(tl >> 2) * (SSTR * 4);
                s_sched[c * SCHW + bse + rank] = (unsigned short)off;
            }
        }
    } else if (warp == 8) {
        // zero regions of BOTH buffers (64 words each)
        for (int i = lane; i < 64; i += 32) {
            s_pl[0][BUFW + i] = 0.0f;
            s_pl[1][BUFW + i] = 0.0f;
        }
    }
    if (tid < LNK) s_inv[tid] = 1.0f / (caps[tid] + EPSF);

    // ------------- STS chunk 0 into buffer 0 -------------------------------
    {
        const int wb = lane * SSTR + warp * 2;
        ((float2*)&s_pl[0][0])[(0 * PLW + wb) >> 1] = make_float2(ra.x * da, rb.x * db);
        ((float2*)&s_pl[0][0])[(1 * PLW + wb) >> 1] = make_float2(ra.y * da, rb.y * db);
        ((float2*)&s_pl[0][0])[(2 * PLW + wb) >> 1] = make_float2(ra.z * da, rb.z * db);
        ((float2*)&s_pl[0][0])[(3 * PLW + wb) >> 1] = make_float2(ra.w * da, rb.w * db);
    }
    __syncthreads();

    // ------------- main loop: LDG(c+1) | gather(c) | STS(c+1) | sync ------
    unsigned long long acc0 = 0ull, acc1 = 0ull;

    #pragma unroll 1
    for (int c = 0; c < NCH; ++c) {
        if (c < NCH - 1) {
            const int gg = (c + 1) * 32 + lane;
            const int r0 = base + warp, r1 = base + warp + PAIRS;
            const bool ok = (gg < DST);
            const bool o0 = ok && (r0 < B), o1 = ok && (r1 < B);
            ra = o0 ? ((const float4*)pred)[(size_t)r0 * DST + gg] : make_float4(0,0,0,0);
            rb = o1 ? ((const float4*)pred)[(size_t)r1 * DST + gg] : make_float4(0,0,0,0);
            da = o0 ? dem[(size_t)r0 * DST + gg] : 0.0f;
            db = o1 ? dem[(size_t)r1 * DST + gg] : 0.0f;
        }

        // gather chunk c from buffer (c&1); warp owns bin = warp
        {
            const unsigned lbase = pl32 + (unsigned)((c & 1) * BUFB) + (unsigned)(lane << 3);
            const unsigned short* sc = &s_sched[c * SCHW];
            int k = s_off[c][warp];
            const int hi = s_off[c][warp + 1];
            #pragma unroll 2
            for (; k < hi; k += 2) {
                const unsigned o0 = sc[k];
                const unsigned o1 = sc[k + 1];
                acc0 = addx2(acc0, lds64(lbase + o0));
                acc1 = addx2(acc1, lds64(lbase + o1));
            }
        }

        if (c < NCH - 1) {
            float* bp = &s_pl[(c + 1) & 1][0];
            const int wb = lane * SSTR + warp * 2;
            ((float2*)bp)[(0 * PLW + wb) >> 1] = make_float2(ra.x * da, rb.x * db);
            ((float2*)bp)[(1 * PLW + wb) >> 1] = make_float2(ra.y * da, rb.y * db);
            ((float2*)bp)[(2 * PLW + wb) >> 1] = make_float2(ra.z * da, rb.z * db);
            ((float2*)bp)[(3 * PLW + wb) >> 1] = make_float2(ra.w * da, rb.w * db);
        }
        __syncthreads();
    }

    // ------------- stats ----------------------------------------------------
    {
        const unsigned long long t = addx2(acc0, acc1);
        const float lo = __uint_as_float((unsigned)(t & 0xffffffffull));
        const float hi = __uint_as_float((unsigned)(t >> 32));
        if (lane < PAIRS) {
            s_nl[lane * 17 + warp] = lo;               // row = lane
            s_nl[(lane + PAIRS) * 17 + warp] = hi;     // row = lane + 16
        }
    }
    __syncthreads();

    float lsum = 0.0f;
    {
        const int rid = (warp << 1) + (lane >> 4);     // 0..31 covers block
        const int j = lane & 15;
        const int brow = base + rid;
        const bool rok = (brow < B);
        const float u   = rok ? s_nl[rid * 17 + j] * s_inv[j] : 0.0f;
        const float cur = rok ? clu[(size_t)brow * LNK + j] : 0.0f;

        float sm = u;
        #pragma unroll
        for (int off = 1; off < 16; off <<= 1)
            sm += __shfl_xor_sync(0xffffffffu, sm, off);
        const float mean = sm * (1.0f / 16.0f);

        const float dv = u - mean;
        float q2  = dv * dv;
        float dot = u * cur;
        float mx  = u;
        #pragma unroll
        for (int off = 1; off < 16; off <<= 1) {
            q2  += __shfl_xor_sync(0xffffffffu, q2, off);
            dot += __shfl_xor_sync(0xffffffffu, dot, off);
            mx   = fmaxf(mx, __shfl_xor_sync(0xffffffffu, mx, off));
        }
        if (j == 0 && rok)
            lsum = 0.3f * (q2 * (1.0f / 15.0f)) + 0.5f * dot + 0.2f * mx;
    }
    lsum += __shfl_xor_sync(0xffffffffu, lsum, 16);
    if (lane == 0) s_loss[warp] = lsum;
    __syncthreads();

    // ------------- deterministic single-launch reduction --------------------
    if (tid == 0) {
        float t = 0.0f;
        #pragma unroll
        for (int w = 0; w < 16; ++w) t += s_loss[w];
        g_partials[blockIdx.x] = t;
        __threadfence();
        const unsigned old = atomicAdd(&g_count, 1u);
        s_last = (old == (unsigned)(nb - 1));
    }
    __syncthreads();

    if (s_last) {
        float v = 0.0f;
        for (int i = tid; i < nb; i += THR) v += __ldcg(&g_partials[i]);
        s_fin[tid] = v;
        __syncthreads();
        #pragma unroll
        for (int st = 256; st > 0; st >>= 1) {
            if (tid < st) s_fin[tid] += s_fin[tid + st];
            __syncthreads();
        }
        if (tid == 0) {
            out[0] = s_fin[0] * invB;
            g_count = 0;
        }
    }
}

extern "C" void kernel_launch(void* const* d_in, const int* in_sizes, int n_in,
                              void* d_out, int out_size)
{
    const float* pred = (const float*)d_in[0];
    const float* dem  = (const float*)d_in[1];
    const float* clu  = (const float*)d_in[2];
    const float* caps = (const float*)d_in[3];
    const int*   t2l  = (const int*)d_in[4];
    float* out = (float*)d_out;

    const int B  = in_sizes[0] / TUN;           // 16384
    int nb = (B + ROWS - 1) / ROWS;             // 512
    if (nb > 512) nb = 512;

    loss_kernel<<<nb, THR>>>(pred, dem, clu, caps, t2l, out, B, nb, 1.0f / (float)B);
}

// round 8
// speedup vs baseline: 1.5087x; 1.5087x over previous
#include <cuda_runtime.h>

#define EPSF 1e-8f
#define LNK   16
#define DST   255
#define TUN   1020
#define NCH   8
#define PAIRS 28          // row pairs per block
#define ROWS  56
#define SSTR  58          // words per group slot (28 pairs*2 + 2 pad); 8B stride 29 odd
#define PLW   (32*SSTR)   // 1856 words per plane
#define ZW    (4*PLW)     // zero region start (word 7424)
#define ZBYTE (ZW*4)      // 29696 byte offset of zero region, fits u16
#define SCHW  144
#define THR   512

__device__ float    g_partials[512];
__device__ unsigned g_count;   // zero-init; last block resets (deterministic)

__device__ __forceinline__ unsigned long long lds64(unsigned a) {
    unsigned long long v;
    asm volatile("ld.shared.b64 %0, [%1];" : "=l"(v) : "r"(a));
    return v;
}
__device__ __forceinline__ unsigned long long addx2(unsigned long long a,
                                                    unsigned long long b) {
    unsigned long long r;
    asm("add.rn.f32x2 %0, %1, %2;" : "=l"(r) : "l"(a), "l"(b));
    return r;
}

__global__ __launch_bounds__(THR, 2) void loss_kernel(
    const float* __restrict__ pred,   // [B,1020]
    const float* __restrict__ dem,    // [B,255]
    const float* __restrict__ clu,    // [B,16]
    const float* __restrict__ caps,   // [16]
    const int*   __restrict__ t2l,    // [1020]
    float* __restrict__ out,
    int B, int nb, float invB)
{
    __shared__ float s_pl[ZW + 64];                 // planes + 64-word zero region
    __shared__ unsigned short s_sched[NCH * SCHW];
    __shared__ int   s_off[NCH][17];
    __shared__ int   s_cur[NCH][17];
    __shared__ float s_nl[ROWS * 17];
    __shared__ float s_inv[LNK];
    __shared__ float s_loss[16];
    __shared__ float s_fin[THR];
    __shared__ int   s_last;

    const int tid  = threadIdx.x;
    const int warp = tid >> 5;          // 0..15
    const int lane = tid & 31;
    const int base = blockIdx.x * ROWS;
    const unsigned pl32 = (unsigned)__cvta_generic_to_shared(s_pl);

    // Two register slots of staged PRODUCTS (chunk parity): [u][plane]
    float2 p0[2][4], p1[2][4];

    // load chunk ch and multiply into products P[u][plane]
    #define LOADMUL(ch, P)                                                        \
    {                                                                             \
        const int gg = (ch) * 32 + lane;                                          \
        _Pragma("unroll")                                                         \
        for (int u = 0; u < 2; ++u) {                                             \
            const int pr = warp + 16 * u;                                         \
            const int r0 = base + pr, r1 = r0 + PAIRS;                            \
            const bool ok = (pr < PAIRS) && (gg < DST);                           \
            const bool o0 = ok && (r0 < B), o1 = ok && (r1 < B);                  \
            float4 ra = o0 ? ((const float4*)pred)[(size_t)r0 * DST + gg]         \
                           : make_float4(0,0,0,0);                                \
            float4 rb = o1 ? ((const float4*)pred)[(size_t)r1 * DST + gg]         \
                           : make_float4(0,0,0,0);                                \
            float  da = o0 ? dem[(size_t)r0 * DST + gg] : 0.0f;                   \
            float  db = o1 ? dem[(size_t)r1 * DST + gg] : 0.0f;                   \
            P[u][0] = make_float2(ra.x * da, rb.x * db);                          \
            P[u][1] = make_float2(ra.y * da, rb.y * db);                          \
            P[u][2] = make_float2(ra.z * da, rb.z * db);                          \
            P[u][3] = make_float2(ra.w * da, rb.w * db);                          \
        }                                                                         \
    }

    #define STSCHUNK(P)                                                           \
    {                                                                             \
        _Pragma("unroll")                                                         \
        for (int u = 0; u < 2; ++u) {                                             \
            const int pr = warp + 16 * u;                                         \
            if (pr < PAIRS) {                                                     \
                const int wb = lane * SSTR + pr * 2;                              \
                ((float2*)s_pl)[(0 * PLW + wb) >> 1] = P[u][0];                   \
                ((float2*)s_pl)[(1 * PLW + wb) >> 1] = P[u][1];                   \
                ((float2*)s_pl)[(2 * PLW + wb) >> 1] = P[u][2];                   \
                ((float2*)s_pl)[(3 * PLW + wb) >> 1] = P[u][3];                   \
            }                                                                     \
        }                                                                         \
    }

    #define GATHER(ch)                                                            \
    {                                                                             \
        const unsigned lbase = pl32 + (unsigned)(lane << 3);                      \
        const unsigned short* sc = &s_sched[(ch) * SCHW];                         \
        int k = s_off[(ch)][warp];                                                \
        const int hi = s_off[(ch)][warp + 1];                                     \
        _Pragma("unroll 2")                                                       \
        for (; k < hi; k += 2) {                                                  \
            const unsigned o0 = sc[k];                                            \
            const unsigned o1 = sc[k + 1];                                        \
            acc0 = addx2(acc0, lds64(lbase + o0));                                \
            acc1 = addx2(acc1, lds64(lbase + o1));                                \
        }                                                                         \
    }

    // ------------- prologue LDGs: chunks 0 and 1 ---------------------------
    LOADMUL(0, p0);
    LOADMUL(1, p1);

    // ------------- schedule build: warp c (<8) sorts chunk c ---------------
    if (warp < 8) {
        const int c = warp;
        if (lane < 17) s_cur[c][lane] = 0;
        int bins[4];
        #pragma unroll
        for (int q = 0; q < 4; ++q) {
            const int t = c * 128 + q * 32 + lane;
            bins[q] = (t < TUN) ? t2l[t] : 16;
        }
        __syncwarp();
        #pragma unroll
        for (int q = 0; q < 4; ++q) {
            const unsigned peers = __match_any_sync(0xffffffffu, bins[q]);
            const int rank = __popc(peers & ((1u << lane) - 1u));
            if (rank == 0) s_cur[c][bins[q]] += __popc(peers);
            __syncwarp();
        }
        if (lane < 17) {                           // padded exclusive scan
            int o = 0;
            for (int i = 0; i < lane; ++i) o += (s_cur[c][i] + 1) & ~1;
            s_off[c][lane] = o;
        }
        __syncwarp();
        for (int i = lane; i < SCHW; i += 32)
            s_sched[c * SCHW + i] = (unsigned short)ZBYTE;   // dummy -> zeros
        if (lane < 17) s_cur[c][lane] = s_off[c][lane];
        __syncwarp();
        #pragma unroll
        for (int q = 0; q < 4; ++q) {
            const unsigned peers = __match_any_sync(0xffffffffu, bins[q]);
            const int rank = __popc(peers & ((1u << lane) - 1u));
            const int bse  = s_cur[c][bins[q]];
            __syncwarp();
            if (rank == 0) s_cur[c][bins[q]] = bse + __popc(peers);
            __syncwarp();
            if (bins[q] < 16) {
                const int tl = q * 32 + lane;
                const unsigned off = (unsigned)(tl & 3) * (PLW * 4)
                                   + (unsigned)(tl >> 2) * (SSTR * 4);
                s_sched[c * SCHW + bse + rank] = (unsigned short)off;
            }
        }
    } else if (warp == 8) {
        for (int i = lane; i < 64; i += 32) s_pl[ZW + i] = 0.0f;   // zero region
    }
    if (tid < LNK) s_inv[tid] = 1.0f / (caps[tid] + EPSF);

    // ------------- STS chunk 0, then pipeline -------------------------------
    STSCHUNK(p0);
    __syncthreads();

    unsigned long long acc0 = 0ull, acc1 = 0ull;

    #pragma unroll 1
    for (int cc = 0; cc < NCH; cc += 2) {
        // ---- c = cc (even) : slot0 free after its STS pre-loop/last iter ----
        if (cc + 2 < NCH) LOADMUL(cc + 2, p0);
        GATHER(cc);
        __syncthreads();
        STSCHUNK(p1);                    // chunk cc+1, loaded one chunk ago
        __syncthreads();

        // ---- c = cc + 1 (odd) ----
        if (cc + 3 < NCH) LOADMUL(cc + 3, p1);
        GATHER(cc + 1);
        if (cc + 2 < NCH) {
            __syncthreads();
            STSCHUNK(p0);                // chunk cc+2
            __syncthreads();
        }
    }

    // ------------- stats ----------------------------------------------------
    {
        const unsigned long long t = addx2(acc0, acc1);
        const float lo = __uint_as_float((unsigned)(t & 0xffffffffull));
        const float hi = __uint_as_float((unsigned)(t >> 32));
        if (lane < PAIRS) {
            s_nl[lane * 17 + warp] = lo;               // row = lane
            s_nl[(lane + PAIRS) * 17 + warp] = hi;     // row = lane + 28
        }
    }
    __syncthreads();

    float lsum = 0.0f;
    #pragma unroll
    for (int p = 0; p < 2; ++p) {
        const int rid = p * 32 + (warp << 1) + (lane >> 4);
        const int j = lane & 15;
        const int brow = base + rid;
        const bool rok = (rid < ROWS) && (brow < B);
        const float u   = rok ? s_nl[rid * 17 + j] * s_inv[j] : 0.0f;
        const float cur = rok ? clu[(size_t)brow * LNK + j] : 0.0f;

        float sm = u;
        #pragma unroll
        for (int off = 1; off < 16; off <<= 1)
            sm += __shfl_xor_sync(0xffffffffu, sm, off);
        const float mean = sm * (1.0f / 16.0f);

        const float dv = u - mean;
        float q2  = dv * dv;
        float dot = u * cur;
        float mx  = u;
        #pragma unroll
        for (int off = 1; off < 16; off <<= 1) {
            q2  += __shfl_xor_sync(0xffffffffu, q2, off);
            dot += __shfl_xor_sync(0xffffffffu, dot, off);
            mx   = fmaxf(mx, __shfl_xor_sync(0xffffffffu, mx, off));
        }
        if (j == 0 && rok)
            lsum += 0.3f * (q2 * (1.0f / 15.0f)) + 0.5f * dot + 0.2f * mx;
    }
    lsum += __shfl_xor_sync(0xffffffffu, lsum, 16);
    if (lane == 0) s_loss[warp] = lsum;
    __syncthreads();

    // ------------- deterministic single-launch reduction --------------------
    if (tid == 0) {
        float t = 0.0f;
        #pragma unroll
        for (int w = 0; w < 16; ++w) t += s_loss[w];
        g_partials[blockIdx.x] = t;
        __threadfence();
        const unsigned old = atomicAdd(&g_count, 1u);
        s_last = (old == (unsigned)(nb - 1));
    }
    __syncthreads();

    if (s_last) {
        float v = 0.0f;
        for (int i = tid; i < nb; i += THR) v += __ldcg(&g_partials[i]);
        s_fin[tid] = v;
        __syncthreads();
        #pragma unroll
        for (int st = 256; st > 0; st >>= 1) {
            if (tid < st) s_fin[tid] += s_fin[tid + st];
            __syncthreads();
        }
        if (tid == 0) {
            out[0] = s_fin[0] * invB;
            g_count = 0;
        }
    }
}

extern "C" void kernel_launch(void* const* d_in, const int* in_sizes, int n_in,
                              void* d_out, int out_size)
{
    const float* pred = (const float*)d_in[0];
    const float* dem  = (const float*)d_in[1];
    const float* clu  = (const float*)d_in[2];
    const float* caps = (const float*)d_in[3];
    const int*   t2l  = (const int*)d_in[4];
    float* out = (float*)d_out;

    const int B  = in_sizes[0] / TUN;           // 16384
    int nb = (B + ROWS - 1) / ROWS;             // 293
    if (nb > 512) nb = 512;

    loss_kernel<<<nb, THR>>>(pred, dem, clu, caps, t2l, out, B, nb, 1.0f / (float)B);
}